// round 14
// baseline (speedup 1.0000x reference)
#include <cuda_runtime.h>

// DTW loss: B=16, C=8, T=512 -> 128 independent 512x512 DTW DPs.
// R14: CO-RESIDENCY. One block = 256 threads = 2 problems. Warps 0-3 run
//   problem A, warps 4-7 problem B; warp w and w+4 share an SMSP (wid%4),
//   so each scheduler interleaves two independent DP chains -> stall slots
//   of one warp are filled by the other (issue was 40%, 115 cyc/ss exposed).
// Per-problem structure = R13 (best: 28.7us): lane owns 4 cols, superstep =
//   4 rows x 4 cols, sigma = lane + 39*pwarp, groups of 4 ss with one
//   combined sentinel check, SHFLs interleaved after each row (latency
//   hidden), BIG-fill handoff (fill carries bit-exact BIG, drain garbage
//   never consumed), slot shift +1 with 8-slot BIG guard prefix.

#define TT    512
#define IWS   39
#define SIGMX (31 + 3 * IWS)       // 148
#define NSS   (TT / 4 + SIGMX)     // 276 supersteps
#define NG    (NSS / 4)            // 69 groups
#define GUARD 8
#define REG   (GUARD + NSS)
#define XS4   (SIGMX + TT / 4 + SIGMX)    // 424 float4 per problem
#define HB4   (4 + 3 * REG)               // 856 float4 per problem
#define BIGF  1e30f

__device__ float        g_partials[128];
__device__ unsigned int g_counter = 0;

#define ROW(xi_, L_, cO_) do {                                                 \
    float m;                                                                   \
    m = fminf(up0, lprev); const float t0 = fabsf((xi_) - y0) + fminf((L_), m);\
    m = fminf(up1, up0 );  const float t1 = fabsf((xi_) - y1) + fminf(t0, m);  \
    m = fminf(up2, up1 );  const float t2 = fabsf((xi_) - y2) + fminf(t1, m);  \
    m = fminf(up3, up2 );  const float t3 = fabsf((xi_) - y3) + fminf(t2, m);  \
    up0 = t0; up1 = t1; up2 = t2; up3 = t3; lprev = (L_); cO_ = t3;            \
} while (0)

#define SSP(xq_, hq_, k_) do {                                                 \
    ROW(xq_.x, L0, c0);                                                        \
    float n0 = __shfl_up_sync(0xffffffffu, c0, 1);                             \
    ROW(xq_.y, L1, c1);                                                        \
    float n1 = __shfl_up_sync(0xffffffffu, c1, 1);                             \
    ROW(xq_.z, L2, c2);                                                        \
    float n2 = __shfl_up_sync(0xffffffffu, c2, 1);                             \
    ROW(xq_.w, L3, c3);                                                        \
    float n3 = __shfl_up_sync(0xffffffffu, c3, 1);                             \
    if (lane == 0) { n0 = hq_.x; n1 = hq_.y; n2 = hq_.z; n3 = hq_.w; }         \
    if (prod) qq[k_] = make_float4(c0, c1, c2, c3);                            \
    L0 = n0; L1 = n1; L2 = n2; L3 = n3;                                        \
} while (0)

#define FIXSLOT(h_, k_) do {                                                   \
    volatile float* vp = (volatile float*)(pp + (k_));                         \
    float w = vp[3];                                                           \
    while (w < 0.0f) { w = vp[3]; }                                            \
    (h_).x = vp[0]; (h_).y = vp[1]; (h_).z = vp[2]; (h_).w = w;                \
} while (0)

__global__ __launch_bounds__(256, 1)
void dtw_fused_kernel(const float* __restrict__ inputs,
                      const float* __restrict__ targets,
                      float* __restrict__ out) {
    const int tid   = threadIdx.x;          // 0..255
    const int lane  = tid & 31;
    const int warp  = tid >> 5;             // 0..7
    const int prob  = warp >> 2;            // 0 = A, 1 = B
    const int pwarp = warp & 3;             // warp within problem
    const int ptid  = tid & 127;            // thread within problem
    const int p     = blockIdx.x * 2 + prob;         // global pair 0..127
    const float* x  = inputs + p * TT;
    const int sig   = lane + IWS * pwarp;

    __shared__ float4 xsbuf[2 * XS4];
    __shared__ float4 handbuf[2 * HB4];

    float4* const xs = xsbuf + prob * XS4;
    float4* const hb = handbuf + prob * HB4;

    {   // init smem (each 128-thread half inits its own problem's buffers)
        float* xf = (float*)xs;
        const int PRE = SIGMX * 4;
        for (int k = ptid; k < PRE; k += 128) xf[k] = 0.0f;
        for (int k = ptid; k < PRE; k += 128) xf[PRE + TT + k] = 0.0f;
        for (int k = ptid; k < TT;  k += 128) xf[PRE + k] = x[k];
        float* hf = (float*)hb;
        for (int k = ptid; k < HB4 * 4; k += 128) hf[k] = -1.0f;
    }
    __syncthreads();
    {   // guards -> BIG (warp0 block + each region's 8-slot prefix)
        float* hf = (float*)hb;
        for (int k = ptid; k < 16; k += 128) hf[k] = BIGF;
        for (int r = 0; r < 3; ++r)
            for (int k = ptid; k < GUARD * 4; k += 128)
                hf[(4 + r * REG) * 4 + k] = BIGF;
    }

    const float4 yq = ((const float4*)(targets + p * TT))[ptid];
    const float y0 = yq.x, y1 = yq.y, y2 = yq.z, y3 = yq.w;

    float up0 = BIGF, up1 = BIGF, up2 = BIGF, up3 = BIGF;
    float lprev = (ptid == 0) ? 0.0f : BIGF;
    float c0 = BIGF, c1 = BIGF, c2 = BIGF, c3 = BIGF;
    float L0 = BIGF, L1 = BIGF, L2 = BIGF, L3 = BIGF;

    const bool prod = (lane == 31 && pwarp < 3);
    // Consumer base: region start (logical slot -8) shifted +1 (L's made at
    // ss t feed ss t+1). Group g loads logical slots 4g-7..4g-4 (producer
    // lead >= 4 ss -> check cold). pwarp0 frozen on its BIG block.
    float4* pp = (pwarp > 0) ? (hb + 4 + (pwarp - 1) * REG + 1) : hb;
    const int pinc = (pwarp > 0) ? 4 : 0;
    float4* qq = hb + 4 + pwarp * REG + GUARD;
    const float4* xp = xs + SIGMX - sig;

    __syncthreads();

    for (int g = 0; g < NG; ++g) {
        float4 hq0 = pp[0], hq1 = pp[1], hq2 = pp[2], hq3 = pp[3];
        if ((hq0.w < 0.0f) | (hq1.w < 0.0f) | (hq2.w < 0.0f) | (hq3.w < 0.0f)) {
            FIXSLOT(hq0, 0); FIXSLOT(hq1, 1); FIXSLOT(hq2, 2); FIXSLOT(hq3, 3);
        }

        const float4 xq0 = xp[0], xq1 = xp[1], xq2 = xp[2], xq3 = xp[3];

        SSP(xq0, hq0, 0);
        SSP(xq1, hq1, 1);
        SSP(xq2, hq2, 2);
        SSP(xq3, hq3, 3);

        pp += pinc; qq += 4; xp += 4;
    }

    // ptid 127 (sig = 148): last valid ss = 275; c3 = dtw[512][512].
    if (ptid == 127) {
        g_partials[p] = c3 * (1.0f / (float)TT);
        __threadfence();
        unsigned int old = atomicAdd(&g_counter, 1u);
        if (old == 127u) {            // 128 finishers total (2 per block)
            volatile float* gp = g_partials;
            float sum = 0.0f;
            #pragma unroll 16
            for (int k = 0; k < 128; ++k) sum += gp[k];
            out[0] = sum * 0.125f;                       // (1/C) * sum_b
            *(volatile unsigned int*)&g_counter = 0;     // reset for replay
        }
    }
}

extern "C" void kernel_launch(void* const* d_in, const int* in_sizes, int n_in,
                              void* d_out, int out_size) {
    const float* inputs  = (const float*)d_in[0];
    const float* targets = (const float*)d_in[1];
    float* out = (float*)d_out;
    (void)in_sizes; (void)n_in; (void)out_size;

    dtw_fused_kernel<<<64, 256>>>(inputs, targets, out);
}

// round 15
// speedup vs baseline: 1.1532x; 1.1532x over previous
#include <cuda_runtime.h>

// DTW loss: B=16, C=8, T=512 -> 128 independent 512x512 DTW DPs.
// One block (128 thr / 4 warps) per pair; lane owns 4 DP cols; superstep =
// 4 rows x 4 cols; sigma = lane + 43*warp; groups of 4 ss, one combined
// sentinel check per group; shfls interleaved after each row (R13 base).
// R15a: min-tree reassociation. col-0 min = min(min(L,lprev), up0); both L
//   and lprev are known since the previous ss, so a_r = fminf(L_r, L_{r-1})
//   is precomputed off-chain -> row-to-row chain = FMNMX+FADD only.
// R15b: group-ahead prefetch of x and handoff slots (~600cy cover). IWS
//   39->43 (slot lag 12, 12-slot BIG guard) so the early read still lands
//   >= 3 ss behind the producer -> sentinel check remains cold.
// BIG-fill handoff: fill carries bit-exact BIG (1e30+c==1e30 in fp32),
//   warp0 polls a frozen BIG block, drain garbage >= 0 and never consumed
//   in-window (slot boundaries == producer's first/last valid publishes).

#define TT    512
#define IWS   43
#define SIGMX (31 + 3 * IWS)       // 160
#define NSS   (TT / 4 + SIGMX)     // 288 supersteps
#define NG    (NSS / 4)            // 72 groups
#define GUARD 12                   // slot lag
#define REG   (GUARD + NSS)        // 300 float4 per producer region
#define XS4   (2 * SIGMX + TT / 4 + 4)   // 452 float4
#define BIGF  1e30f

__device__ float        g_partials[128];
__device__ unsigned int g_counter = 0;

// One DP row: 4 cells. a_ = precomputed min(left, diag) for col 0.
#define ROW(xi_, a_, cO_) do {                                                 \
    const float t0 = fabsf((xi_) - y0) + fminf((a_), up0);                     \
    float m;                                                                   \
    m = fminf(up1, up0); const float t1 = fabsf((xi_) - y1) + fminf(t0, m);    \
    m = fminf(up2, up1); const float t2 = fabsf((xi_) - y2) + fminf(t1, m);    \
    m = fminf(up3, up2); const float t3 = fabsf((xi_) - y3) + fminf(t2, m);    \
    up0 = t0; up1 = t1; up2 = t2; up3 = t3; cO_ = t3;                          \
} while (0)

// One superstep. Consumes a0..a3; produces a0..a3 for the next ss from the
// interleaved shfls (lane0 <- hq_, the cross-warp slot for the NEXT ss).
#define SSP(xq_, hq_, k_) do {                                                 \
    ROW(xq_.x, a0, c0);                                                        \
    float n0 = __shfl_up_sync(0xffffffffu, c0, 1);                             \
    ROW(xq_.y, a1, c1);                                                        \
    float n1 = __shfl_up_sync(0xffffffffu, c1, 1);                             \
    ROW(xq_.z, a2, c2);                                                        \
    float n2 = __shfl_up_sync(0xffffffffu, c2, 1);                             \
    ROW(xq_.w, a3, c3);                                                        \
    float n3 = __shfl_up_sync(0xffffffffu, c3, 1);                             \
    if (lane == 0) { n0 = hq_.x; n1 = hq_.y; n2 = hq_.z; n3 = hq_.w; }         \
    if (prod) qq[k_] = make_float4(c0, c1, c2, c3);                            \
    a0 = fminf(n0, lvprev); a1 = fminf(n1, n0);                                \
    a2 = fminf(n2, n1);     a3 = fminf(n3, n2);                                \
    lvprev = n3;                                                               \
} while (0)

// Cold path: volatile re-poll of one slot until its .w leaves sentinel.
#define FIXSLOT(h_, k_) do {                                                   \
    volatile float* vp = (volatile float*)(pp + (k_));                         \
    float w = vp[3];                                                           \
    while (w < 0.0f) { w = vp[3]; }                                            \
    (h_).x = vp[0]; (h_).y = vp[1]; (h_).z = vp[2]; (h_).w = w;                \
} while (0)

__global__ __launch_bounds__(128, 1)
void dtw_fused_kernel(const float* __restrict__ inputs,
                      const float* __restrict__ targets,
                      float* __restrict__ out) {
    const int p    = blockIdx.x;
    const float* x = inputs + p * TT;
    const int tid  = threadIdx.x;
    const int lane = tid & 31;
    const int warp = tid >> 5;
    const int sig  = lane + IWS * warp;

    __shared__ float4 xsbuf[XS4];                  // x rows, zero-padded
    __shared__ float4 handbuf[4 + 3 * REG];        // BIG block + 3 regions

    {   // init smem
        float* xf = (float*)xsbuf;
        const int PRE = SIGMX * 4;
        for (int k = tid; k < PRE; k += 128) xf[k] = 0.0f;
        for (int k = PRE + TT + tid; k < XS4 * 4; k += 128) xf[k] = 0.0f;
        for (int k = tid; k < TT; k += 128) xf[PRE + k] = x[k];
        float* hf = (float*)handbuf;
        for (int k = tid; k < (4 + 3 * REG) * 4; k += 128) hf[k] = -1.0f;
    }
    __syncthreads();
    {   // guards -> BIG: warp0 block + each region's 12-slot prefix
        float* hf = (float*)handbuf;
        for (int k = tid; k < 16; k += 128) hf[k] = BIGF;
        for (int r = 0; r < 3; ++r)
            for (int k = tid; k < GUARD * 4; k += 128)
                hf[(4 + r * REG) * 4 + k] = BIGF;
    }

    const float4 yq = ((const float4*)(targets + p * TT))[tid];
    const float y0 = yq.x, y1 = yq.y, y2 = yq.z, y3 = yq.w;

    float up0 = BIGF, up1 = BIGF, up2 = BIGF, up3 = BIGF;
    float c0 = BIGF, c1 = BIGF, c2 = BIGF, c3 = BIGF;
    // a_r = min(left_r, diag_r) for the 4 rows of ss 0; tid0's a0 = dtw[0][0].
    float a0 = (tid == 0) ? 0.0f : BIGF;
    float a1 = BIGF, a2 = BIGF, a3 = BIGF;
    float lvprev = BIGF;

    const bool prod = (lane == 31 && warp < 3);
    // Consumer: L's made at ss t feed ss t+1 -> slot t-11; region index =
    // GUARD + slot, so base = region + 1. warp0 frozen on its BIG block.
    float4* pp = (warp > 0) ? (handbuf + 4 + (warp - 1) * REG + 1) : handbuf;
    const int pinc = (warp > 0) ? 4 : 0;
    float4* qq = handbuf + 4 + warp * REG + GUARD;   // producer slot 0
    const float4* xp = xsbuf + SIGMX - sig;

    __syncthreads();

    // Preload group 0 (x rows + handoff slots; slots -11..-8 are guards).
    float4 xq0 = xp[0], xq1 = xp[1], xq2 = xp[2], xq3 = xp[3];
    float4 hq0 = pp[0], hq1 = pp[1], hq2 = pp[2], hq3 = pp[3];

    for (int g = 0; g < NG; ++g) {
        // Fix current group's slots if any prefetch caught a sentinel (cold:
        // prefetch ran >= 3 ss behind the producer).
        if ((hq0.w < 0.0f) | (hq1.w < 0.0f) | (hq2.w < 0.0f) | (hq3.w < 0.0f)) {
            FIXSLOT(hq0, 0); FIXSLOT(hq1, 1); FIXSLOT(hq2, 2); FIXSLOT(hq3, 3);
        }

        // Prefetch group g+1 (covered by this group's ~600 cycles of work).
        xp += 4; pp += pinc;
        const float4 xn0 = xp[0], xn1 = xp[1], xn2 = xp[2], xn3 = xp[3];
        const float4 hn0 = pp[0], hn1 = pp[1], hn2 = pp[2], hn3 = pp[3];

        SSP(xq0, hq0, 0);
        SSP(xq1, hq1, 1);
        SSP(xq2, hq2, 2);
        SSP(xq3, hq3, 3);

        qq += 4;
        xq0 = xn0; xq1 = xn1; xq2 = xn2; xq3 = xn3;
        hq0 = hn0; hq1 = hn1; hq2 = hn2; hq3 = hn3;
    }

    // tid 127 (sig = 160): last valid ss = 287 = NSS-1; c3 = dtw[512][512].
    if (tid == 127) {
        g_partials[p] = c3 * (1.0f / (float)TT);
        __threadfence();
        unsigned int old = atomicAdd(&g_counter, 1u);
        if (old == 127u) {
            volatile float* gp = g_partials;
            float sum = 0.0f;
            #pragma unroll 16
            for (int k = 0; k < 128; ++k) sum += gp[k];
            out[0] = sum * 0.125f;                       // (1/C) * sum_b
            *(volatile unsigned int*)&g_counter = 0;     // reset for replay
        }
    }
}

extern "C" void kernel_launch(void* const* d_in, const int* in_sizes, int n_in,
                              void* d_out, int out_size) {
    const float* inputs  = (const float*)d_in[0];
    const float* targets = (const float*)d_in[1];
    float* out = (float*)d_out;
    (void)in_sizes; (void)n_in; (void)out_size;

    dtw_fused_kernel<<<128, 128>>>(inputs, targets, out);
}